// round 7
// baseline (speedup 1.0000x reference)
#include <cuda_runtime.h>

#define N_ATOMS 320
#define NTHREADS 320
#define NWARPS 10
#define CAPN 96

// cos(sqrt(y)), degree-6 Taylor in y; |abs err| < 1.1e-4 for y in [0, pi^2]
__device__ __forceinline__ float cos_sqrt_poly(float y) {
    float p =  2.08767570e-9f;           // 1/12!
    p = fmaf(p, y, -2.75573192e-7f);     // -1/10!
    p = fmaf(p, y,  2.48015873e-5f);     //  1/8!
    p = fmaf(p, y, -1.38888889e-3f);     // -1/6!
    p = fmaf(p, y,  4.16666667e-2f);     //  1/4!
    p = fmaf(p, y, -0.5f);
    p = fmaf(p, y,  1.0f);
    return p;
}

__global__ __launch_bounds__(NTHREADS, 3)
void featurizer_kernel(const float* __restrict__ atomic_numbers,
                       const float* __restrict__ coords,
                       float* __restrict__ out)
{
    __shared__ float4   nA[CAPN];           // {dx, dy, dz, r2}
    __shared__ float4   nB[CAPN];           // {fc, e01, e05, rs}
    __shared__ float    radC[13][CAPN];     // compacted radial terms
    __shared__ unsigned smask[NWARPS];

    const int i    = blockIdx.x;
    const int tid  = threadIdx.x;           // one thread per atom j
    const int lane = tid & 31;
    const int warp = tid >> 5;

    const float xi = __ldg(&coords[3 * i + 0]);
    const float yi = __ldg(&coords[3 * i + 1]);
    const float zi = __ldg(&coords[3 * i + 2]);
    const float PI2_36 = 0.27415567780803773f;   // (pi/6)^2

    // Zero angular output columns (atomics accumulate into them later;
    // ordering guaranteed by the two barriers below). Col 0 plain write.
    if (tid == 0) out[i * 22 + 0] = __ldg(&atomic_numbers[i]);
    if (tid >= 14 && tid < 22) out[i * 22 + tid] = 0.0f;

    // ---- Phase 1: one j per thread, all in registers ----
    const float dx = xi - __ldg(&coords[3 * tid + 0]);
    const float dy = yi - __ldg(&coords[3 * tid + 1]);
    const float dz = zi - __ldg(&coords[3 * tid + 2]);
    const float r2 = dx * dx + dy * dy + dz * dz;
    const bool pred = (tid != i) && (r2 < 36.0f);
    const unsigned m = __ballot_sync(0xffffffffu, pred);
    if (lane == 0) smask[warp] = m;

    float radv[13];
    float fc = 0.f, e05 = 0.f, e01 = 0.f, rs = 0.f;
    if (pred) {
        rs  = rsqrtf(r2);
        float r = r2 * rs;
        fc  = 0.5f * (cos_sqrt_poly(PI2_36 * r2) + 1.0f);
        e05 = __expf(-0.5f * r2);
        e01 = __expf(-0.1f * r2);
        float e1g2 = e05 * e05, e2g2 = e1g2 * e1g2, e4g2 = e2g2 * e2g2;
        float gsh  = __expf(fmaf(3.0f, r, -4.5f));       // exp(3r - 4.5)
        float f05  = e05 * gsh;                          // exp(-0.5 (r-3)^2)
        float f1 = f05 * f05, f2 = f1 * f1, f4 = f2 * f2;
        float c1 = __cosf(0.5f * r);                     // Chebyshev chain
        float c2 = fmaf(2.f * c1, c1, -1.f);
        float c3 = fmaf(2.f * c1, c2, -c1);
        float c4 = fmaf(2.f * c1, c3, -c2);
        radv[0] = fc;
        radv[1] = e05 * fc;  radv[2] = e1g2 * fc;  radv[3] = e2g2 * fc;  radv[4] = e4g2 * fc;
        radv[5] = f05 * fc;  radv[6] = f1 * fc;    radv[7] = f2 * fc;    radv[8] = f4 * fc;
        radv[9] = c1 * fc;   radv[10] = c2 * fc;   radv[11] = c3 * fc;   radv[12] = c4 * fc;
    }
    __syncthreads();   // barrier A: smask + zero-stores ordered

    // ---- Warp-scan prefix over per-warp counts (no loop over smem) ----
    int cnt = (lane < NWARPS) ? (int)__popc(smask[lane]) : 0;
    int sc = cnt;
    #pragma unroll
    for (int off = 1; off < 16; off <<= 1) {
        int n = __shfl_up_sync(0xffffffffu, sc, off);
        if (lane >= off) sc += n;
    }
    const int M   = __shfl_sync(0xffffffffu, sc, NWARPS - 1);
    const int pfx = __shfl_sync(0xffffffffu, sc - cnt, warp);

    if (pred) {
        int pos = pfx + __popc(m & ((1u << lane) - 1u));
        if (pos < CAPN) {
            nA[pos] = make_float4(dx, dy, dz, r2);
            nB[pos] = make_float4(fc, e01, e05, rs);
            #pragma unroll
            for (int q = 0; q < 13; q++) radC[q][pos] = radv[q];
        }
    }
    __syncthreads();   // barrier B: compacted arrays visible

    const int Mc = (M < CAPN) ? M : CAPN;

    // ---- Radial channel sums: warps own channels (ch = warp, warp+10) ----
    #pragma unroll
    for (int chb = 0; chb < 13; chb += NWARPS) {
        int ch = chb + warp;
        if (ch < 13) {
            float v = 0.f;
            #pragma unroll
            for (int t = 0; t < 3; t++) {
                int idx = lane + 32 * t;
                if (idx < Mc) v += radC[ch][idx];
            }
            #pragma unroll
            for (int off = 16; off > 0; off >>= 1) v += __shfl_down_sync(0xffffffffu, v, off);
            if (lane == 0) out[i * 22 + 1 + ch] = v;
        }
    }

    // ---- Phase 2: angular sums over unordered pairs a>b ----
    float s[8];
    #pragma unroll
    for (int q = 0; q < 8; q++) s[q] = 0.f;

    const int npairs = (Mc * (Mc - 1)) >> 1;
    #pragma unroll 2
    for (int p = tid; p < npairs; p += NTHREADS) {
        // branchless triangular decode: p = a(a-1)/2 + b, a > b
        int a = (int)(0.5f * (1.0f + sqrtf(fmaf(8.0f, (float)p, 1.0f))));
        a -= (((a * (a - 1)) >> 1) > p);
        a += ((((a + 1) * a) >> 1) <= p);
        int b = p - ((a * (a - 1)) >> 1);

        float4 va = nA[a], vb = nA[b];
        float4 wa = nB[a], wb = nB[b];

        float dot = va.x * vb.x + va.y * vb.y + va.z * vb.z;
        float cosv = dot * wa.w * wb.w;
        float R2p  = va.w + vb.w;
        float r2jk = fmaxf(fmaf(-2.0f, dot, R2p), 0.0f);

        float fcjk = (r2jk < 36.0f)
                   ? 0.5f * (cos_sqrt_poly(PI2_36 * r2jk) + 1.0f) : 0.0f;

        float ejk1 = __expf(-0.1f * r2jk);
        float t2 = ejk1 * ejk1, t4 = t2 * t2;
        float ejk5 = t4 * ejk1;                       // exp(-0.5 r2jk)

        float ep1 = wa.y * wb.y;
        float ep5 = wa.z * wb.z;
        float fc2 = wa.x * wb.x;
        float fc3 = fc2 * fcjk;
        float et1 = ep1 * ejk1, et5 = ep5 * ejk5;

        float op = 1.0f + cosv, om = 1.0f - cosv;
        float a1 = om * om;          // (1-c)^2
        float op2 = op * op;
        float a2 = op2 * op2;        // (1+c)^4
        float a3 = a1 * a1;          // (1-c)^4

        float w41 = et1 * fc3, w45 = et5 * fc3;
        float w51 = ep1 * fc2, w55 = ep5 * fc2;
        s[0] += op * w41; s[1] += a1 * w41; s[2] += a2 * w45; s[3] += a3 * w45;
        s[4] += op * w51; s[5] += a1 * w51; s[6] += a2 * w55; s[7] += a3 * w55;
    }

    // ---- Angular reduction: per-warp shfl tree, lane0 REDG into out ----
    const float scl[8] = {1.0f, 0.5f, 0.125f, 0.125f,
                          1.0f, 0.5f, 0.125f, 0.125f};
    #pragma unroll
    for (int q = 0; q < 8; q++) {
        float v = s[q];
        #pragma unroll
        for (int off = 16; off > 0; off >>= 1) v += __shfl_down_sync(0xffffffffu, v, off);
        if (lane == 0) atomicAdd(&out[i * 22 + 14 + q], v * scl[q]);
    }
}

extern "C" void kernel_launch(void* const* d_in, const int* in_sizes, int n_in,
                              void* d_out, int out_size)
{
    const float* atomic_numbers = (const float*)d_in[0]; // [320,1]
    const float* coordinates    = (const float*)d_in[1]; // [320,3]
    float* out = (float*)d_out;                          // [320,22]
    featurizer_kernel<<<N_ATOMS, NTHREADS>>>(atomic_numbers, coordinates, out);
}

// round 8
// speedup vs baseline: 1.0294x; 1.0294x over previous
#include <cuda_runtime.h>

#define N_ATOMS 320
#define NTHREADS 320
#define NWARPS 10
#define CAPN 96

// cos(sqrt(y)), degree-6 Taylor in y; |abs err| < 1.1e-4 for y in [0, pi^2]
__device__ __forceinline__ float cos_sqrt_poly(float y) {
    float p =  2.08767570e-9f;           // 1/12!
    p = fmaf(p, y, -2.75573192e-7f);     // -1/10!
    p = fmaf(p, y,  2.48015873e-5f);     //  1/8!
    p = fmaf(p, y, -1.38888889e-3f);     // -1/6!
    p = fmaf(p, y,  4.16666667e-2f);     //  1/4!
    p = fmaf(p, y, -0.5f);
    p = fmaf(p, y,  1.0f);
    return p;
}

__global__ __launch_bounds__(NTHREADS, 3)
void featurizer_kernel(const float* __restrict__ atomic_numbers,
                       const float* __restrict__ coords,
                       float* __restrict__ out)
{
    __shared__ float4   nA[CAPN];           // {dx, dy, dz, r2}
    __shared__ float4   nB[CAPN];           // {fc, e01, e05, rs}
    __shared__ float    radC[13][CAPN];     // compacted radial terms
    __shared__ unsigned smask[NWARPS];

    const int i    = blockIdx.x;
    const int tid  = threadIdx.x;           // one thread per atom j
    const int lane = tid & 31;
    const int warp = tid >> 5;

    const float xi = __ldg(&coords[3 * i + 0]);
    const float yi = __ldg(&coords[3 * i + 1]);
    const float zi = __ldg(&coords[3 * i + 2]);
    const float PI2_36 = 0.27415567780803773f;   // (pi/6)^2

    // Zero angular output columns (atomics accumulate into them later;
    // ordering guaranteed by the barriers below). Col 0 plain write.
    if (tid == 0) out[i * 22 + 0] = __ldg(&atomic_numbers[i]);
    if (tid >= 14 && tid < 22) out[i * 22 + tid] = 0.0f;

    // ---- Phase 1: one j per thread, all in registers ----
    const float dx = xi - __ldg(&coords[3 * tid + 0]);
    const float dy = yi - __ldg(&coords[3 * tid + 1]);
    const float dz = zi - __ldg(&coords[3 * tid + 2]);
    const float r2 = dx * dx + dy * dy + dz * dz;
    const bool pred = (tid != i) && (r2 < 36.0f);
    const unsigned m = __ballot_sync(0xffffffffu, pred);
    if (lane == 0) smask[warp] = m;

    float radv[13];
    float fc = 0.f, e05 = 0.f, e01 = 0.f, rs = 0.f;
    if (pred) {
        rs  = rsqrtf(r2);
        float r = r2 * rs;
        fc  = 0.5f * (cos_sqrt_poly(PI2_36 * r2) + 1.0f);
        e05 = __expf(-0.5f * r2);
        e01 = __expf(-0.1f * r2);
        float e1g2 = e05 * e05, e2g2 = e1g2 * e1g2, e4g2 = e2g2 * e2g2;
        float gsh  = __expf(fmaf(3.0f, r, -4.5f));       // exp(3r - 4.5)
        float f05  = e05 * gsh;                          // exp(-0.5 (r-3)^2)
        float f1 = f05 * f05, f2 = f1 * f1, f4 = f2 * f2;
        float c1 = __cosf(0.5f * r);                     // Chebyshev chain
        float c2 = fmaf(2.f * c1, c1, -1.f);
        float c3 = fmaf(2.f * c1, c2, -c1);
        float c4 = fmaf(2.f * c1, c3, -c2);
        radv[0] = fc;
        radv[1] = e05 * fc;  radv[2] = e1g2 * fc;  radv[3] = e2g2 * fc;  radv[4] = e4g2 * fc;
        radv[5] = f05 * fc;  radv[6] = f1 * fc;    radv[7] = f2 * fc;    radv[8] = f4 * fc;
        radv[9] = c1 * fc;   radv[10] = c2 * fc;   radv[11] = c3 * fc;   radv[12] = c4 * fc;
    }
    __syncthreads();   // barrier A: smask + zero-stores ordered

    // ---- Warp-scan prefix over per-warp counts ----
    int cnt = (lane < NWARPS) ? (int)__popc(smask[lane]) : 0;
    int sc = cnt;
    #pragma unroll
    for (int off = 1; off < 16; off <<= 1) {
        int n = __shfl_up_sync(0xffffffffu, sc, off);
        if (lane >= off) sc += n;
    }
    const int M   = __shfl_sync(0xffffffffu, sc, NWARPS - 1);
    const int pfx = __shfl_sync(0xffffffffu, sc - cnt, warp);

    if (pred) {
        int pos = pfx + __popc(m & ((1u << lane) - 1u));
        if (pos < CAPN) {
            nA[pos] = make_float4(dx, dy, dz, r2);
            nB[pos] = make_float4(fc, e01, e05, rs);
            #pragma unroll
            for (int q = 0; q < 13; q++) radC[q][pos] = radv[q];
        }
    }
    __syncthreads();   // barrier B: compacted arrays visible

    const int Mc = (M < CAPN) ? M : CAPN;

    // ---- Radial channel sums: warps own channels (ch = warp, warp+10) ----
    #pragma unroll
    for (int chb = 0; chb < 13; chb += NWARPS) {
        int ch = chb + warp;
        if (ch < 13) {
            float v = 0.f;
            #pragma unroll
            for (int t = 0; t < 3; t++) {
                int idx = lane + 32 * t;
                if (idx < Mc) v += radC[ch][idx];
            }
            #pragma unroll
            for (int off = 16; off > 0; off >>= 1) v += __shfl_down_sync(0xffffffffu, v, off);
            if (lane == 0) out[i * 22 + 1 + ch] = v;
        }
    }

    // ---- Phase 2: angular sums over unordered pairs a>b ----
    float s[8];
    #pragma unroll
    for (int q = 0; q < 8; q++) s[q] = 0.f;

    const int npairs = (Mc * (Mc - 1)) >> 1;
    #pragma unroll 2
    for (int p = tid; p < npairs; p += NTHREADS) {
        // branchless triangular decode: p = a(a-1)/2 + b, a > b
        int a = (int)(0.5f * (1.0f + sqrtf(fmaf(8.0f, (float)p, 1.0f))));
        a -= (((a * (a - 1)) >> 1) > p);
        a += ((((a + 1) * a) >> 1) <= p);
        int b = p - ((a * (a - 1)) >> 1);

        float4 va = nA[a], vb = nA[b];
        float4 wa = nB[a], wb = nB[b];

        float dot = va.x * vb.x + va.y * vb.y + va.z * vb.z;
        float cosv = dot * wa.w * wb.w;
        float R2p  = va.w + vb.w;
        float r2jk = fmaxf(fmaf(-2.0f, dot, R2p), 0.0f);

        float fcjk = (r2jk < 36.0f)
                   ? 0.5f * (cos_sqrt_poly(PI2_36 * r2jk) + 1.0f) : 0.0f;

        float ejk1 = __expf(-0.1f * r2jk);
        float t2 = ejk1 * ejk1, t4 = t2 * t2;
        float ejk5 = t4 * ejk1;                       // exp(-0.5 r2jk)

        float ep1 = wa.y * wb.y;
        float ep5 = wa.z * wb.z;
        float fc2 = wa.x * wb.x;
        float fc3 = fc2 * fcjk;
        float et1 = ep1 * ejk1, et5 = ep5 * ejk5;

        float op = 1.0f + cosv, om = 1.0f - cosv;
        float a1 = om * om;          // (1-c)^2
        float op2 = op * op;
        float a2 = op2 * op2;        // (1+c)^4
        float a3 = a1 * a1;          // (1-c)^4

        float w41 = et1 * fc3, w45 = et5 * fc3;
        float w51 = ep1 * fc2, w55 = ep5 * fc2;
        s[0] += op * w41; s[1] += a1 * w41; s[2] += a2 * w45; s[3] += a3 * w45;
        s[4] += op * w51; s[5] += a1 * w51; s[6] += a2 * w55; s[7] += a3 * w55;
    }

    // ---- Angular reduction: multi-channel butterfly (8 ch over 32 lanes) ----
    // Fold channels 8 -> 4 -> 2 -> 1 across lane bits 0..2.
    #pragma unroll
    for (int k = 0; k < 3; k++) {
        const int half = 4 >> k;             // 4, 2, 1
        const bool hi = (lane >> k) & 1;
        #pragma unroll
        for (int q = 0; q < half; q++) {
            float send  = hi ? s[q] : s[q + half];
            float other = __shfl_xor_sync(0xffffffffu, send, 1 << k);
            s[q] = (hi ? s[q + half] : s[q]) + other;
        }
    }
    // Sum the 4 lane-cosets (bits 3, 4).
    s[0] += __shfl_xor_sync(0xffffffffu, s[0], 8);
    s[0] += __shfl_xor_sync(0xffffffffu, s[0], 16);

    if (lane < 8) {
        // channel held by this lane: ch = bit0*4 + bit1*2 + bit2 (bit-reversed)
        int ch = ((lane & 1) << 2) | (lane & 2) | ((lane >> 2) & 1);
        // scale: 2^(1-zeta) (unordered-pair sum): ch%4 -> {1, 0.5, 0.125, 0.125}
        float scl = (ch & 2) ? 0.125f : ((ch & 1) ? 0.5f : 1.0f);
        atomicAdd(&out[i * 22 + 14 + ch], s[0] * scl);
    }
}

extern "C" void kernel_launch(void* const* d_in, const int* in_sizes, int n_in,
                              void* d_out, int out_size)
{
    const float* atomic_numbers = (const float*)d_in[0]; // [320,1]
    const float* coordinates    = (const float*)d_in[1]; // [320,3]
    float* out = (float*)d_out;                          // [320,22]
    featurizer_kernel<<<N_ATOMS, NTHREADS>>>(atomic_numbers, coordinates, out);
}

// round 9
// speedup vs baseline: 1.0606x; 1.0303x over previous
#include <cuda_runtime.h>

#define N_ATOMS 320
#define NTHREADS 320
#define NWARPS 10
#define CAPN 96

// cos(sqrt(y)), degree-6 Taylor in y; |abs err| < 1.1e-4 for y in [0, pi^2]
__device__ __forceinline__ float cos_sqrt_poly(float y) {
    float p =  2.08767570e-9f;           // 1/12!
    p = fmaf(p, y, -2.75573192e-7f);     // -1/10!
    p = fmaf(p, y,  2.48015873e-5f);     //  1/8!
    p = fmaf(p, y, -1.38888889e-3f);     // -1/6!
    p = fmaf(p, y,  4.16666667e-2f);     //  1/4!
    p = fmaf(p, y, -0.5f);
    p = fmaf(p, y,  1.0f);
    return p;
}

__global__ __launch_bounds__(NTHREADS, 3)
void featurizer_kernel(const float* __restrict__ atomic_numbers,
                       const float* __restrict__ coords,
                       float* __restrict__ out)
{
    __shared__ float4   nA[CAPN];           // {dx, dy, dz, r2}
    __shared__ float4   nB[CAPN];           // {fc, e01, e05, rs}
    __shared__ float    radC[13][CAPN];     // compacted radial terms
    __shared__ unsigned smask[NWARPS];

    const int i    = blockIdx.x;
    const int tid  = threadIdx.x;           // one thread per atom j
    const int lane = tid & 31;
    const int warp = tid >> 5;

    const float xi = __ldg(&coords[3 * i + 0]);
    const float yi = __ldg(&coords[3 * i + 1]);
    const float zi = __ldg(&coords[3 * i + 2]);
    const float PI2_36 = 0.27415567780803773f;   // (pi/6)^2

    // Zero angular output columns (atomics accumulate into them after
    // barrier C). Col 0 plain write.
    if (tid == 0) out[i * 22 + 0] = __ldg(&atomic_numbers[i]);
    if (tid >= 14 && tid < 22) out[i * 22 + tid] = 0.0f;

    // ---- Step 1 (all threads): geometry only ----
    const float dx = xi - __ldg(&coords[3 * tid + 0]);
    const float dy = yi - __ldg(&coords[3 * tid + 1]);
    const float dz = zi - __ldg(&coords[3 * tid + 2]);
    const float r2 = dx * dx + dy * dy + dz * dz;
    const bool pred = (tid != i) && (r2 < 36.0f);
    const unsigned m = __ballot_sync(0xffffffffu, pred);
    if (lane == 0) smask[warp] = m;
    __syncthreads();   // barrier A: smask visible

    // Warp-scan prefix over per-warp counts
    int cnt = (lane < NWARPS) ? (int)__popc(smask[lane]) : 0;
    int sc = cnt;
    #pragma unroll
    for (int off = 1; off < 16; off <<= 1) {
        int n = __shfl_up_sync(0xffffffffu, sc, off);
        if (lane >= off) sc += n;
    }
    const int M   = __shfl_sync(0xffffffffu, sc, NWARPS - 1);
    const int pfx = __shfl_sync(0xffffffffu, sc - cnt, warp);

    if (pred) {
        int pos = pfx + __popc(m & ((1u << lane) - 1u));
        if (pos < CAPN) nA[pos] = make_float4(dx, dy, dz, r2);
    }
    __syncthreads();   // barrier B: nA visible

    const int Mc = (M < CAPN) ? M : CAPN;

    // ---- Step 2 (only first Mc threads, ~2 warps): heavy per-neighbor math ----
    if (tid < Mc) {
        float4 v = nA[tid];
        float q2 = v.w;
        float rs  = rsqrtf(q2);
        float r   = q2 * rs;
        float fc  = 0.5f * (cos_sqrt_poly(PI2_36 * q2) + 1.0f);
        float e05 = __expf(-0.5f * q2);
        float e01 = __expf(-0.1f * q2);
        float e1g2 = e05 * e05, e2g2 = e1g2 * e1g2, e4g2 = e2g2 * e2g2;
        float gsh  = __expf(fmaf(3.0f, r, -4.5f));       // exp(3r - 4.5)
        float f05  = e05 * gsh;                          // exp(-0.5 (r-3)^2)
        float f1 = f05 * f05, f2 = f1 * f1, f4 = f2 * f2;
        float c1 = __cosf(0.5f * r);                     // Chebyshev chain
        float c2 = fmaf(2.f * c1, c1, -1.f);
        float c3 = fmaf(2.f * c1, c2, -c1);
        float c4 = fmaf(2.f * c1, c3, -c2);

        nB[tid] = make_float4(fc, e01, e05, rs);
        radC[0][tid]  = fc;
        radC[1][tid]  = e05 * fc;  radC[2][tid]  = e1g2 * fc;
        radC[3][tid]  = e2g2 * fc; radC[4][tid]  = e4g2 * fc;
        radC[5][tid]  = f05 * fc;  radC[6][tid]  = f1 * fc;
        radC[7][tid]  = f2 * fc;   radC[8][tid]  = f4 * fc;
        radC[9][tid]  = c1 * fc;   radC[10][tid] = c2 * fc;
        radC[11][tid] = c3 * fc;   radC[12][tid] = c4 * fc;
    }
    __syncthreads();   // barrier C: nB + radC visible

    // ---- Radial channel sums: warps own channels (ch = warp, warp+10) ----
    #pragma unroll
    for (int chb = 0; chb < 13; chb += NWARPS) {
        int ch = chb + warp;
        if (ch < 13) {
            float v = 0.f;
            #pragma unroll
            for (int t = 0; t < 3; t++) {
                int idx = lane + 32 * t;
                if (idx < Mc) v += radC[ch][idx];
            }
            #pragma unroll
            for (int off = 16; off > 0; off >>= 1) v += __shfl_down_sync(0xffffffffu, v, off);
            if (lane == 0) out[i * 22 + 1 + ch] = v;
        }
    }

    // ---- Phase 2: angular sums over unordered pairs a>b ----
    float s[8];
    #pragma unroll
    for (int q = 0; q < 8; q++) s[q] = 0.f;

    const int npairs = (Mc * (Mc - 1)) >> 1;
    #pragma unroll 2
    for (int p = tid; p < npairs; p += NTHREADS) {
        // branchless triangular decode: p = a(a-1)/2 + b, a > b
        int a = (int)(0.5f * (1.0f + sqrtf(fmaf(8.0f, (float)p, 1.0f))));
        a -= (((a * (a - 1)) >> 1) > p);
        a += ((((a + 1) * a) >> 1) <= p);
        int b = p - ((a * (a - 1)) >> 1);

        float4 va = nA[a], vb = nA[b];
        float4 wa = nB[a], wb = nB[b];

        float dot = va.x * vb.x + va.y * vb.y + va.z * vb.z;
        float cosv = dot * wa.w * wb.w;
        float R2p  = va.w + vb.w;
        float r2jk = fmaxf(fmaf(-2.0f, dot, R2p), 0.0f);

        float fcjk = (r2jk < 36.0f)
                   ? 0.5f * (cos_sqrt_poly(PI2_36 * r2jk) + 1.0f) : 0.0f;

        float ejk1 = __expf(-0.1f * r2jk);
        float t2 = ejk1 * ejk1, t4 = t2 * t2;
        float ejk5 = t4 * ejk1;                       // exp(-0.5 r2jk)

        float ep1 = wa.y * wb.y;
        float ep5 = wa.z * wb.z;
        float fc2 = wa.x * wb.x;
        float fc3 = fc2 * fcjk;
        float et1 = ep1 * ejk1, et5 = ep5 * ejk5;

        float op = 1.0f + cosv, om = 1.0f - cosv;
        float a1 = om * om;          // (1-c)^2
        float op2 = op * op;
        float a2 = op2 * op2;        // (1+c)^4
        float a3 = a1 * a1;          // (1-c)^4

        float w41 = et1 * fc3, w45 = et5 * fc3;
        float w51 = ep1 * fc2, w55 = ep5 * fc2;
        s[0] += op * w41; s[1] += a1 * w41; s[2] += a2 * w45; s[3] += a3 * w45;
        s[4] += op * w51; s[5] += a1 * w51; s[6] += a2 * w55; s[7] += a3 * w55;
    }

    // ---- Angular reduction: multi-channel butterfly (8 ch over 32 lanes) ----
    #pragma unroll
    for (int k = 0; k < 3; k++) {
        const int half = 4 >> k;             // 4, 2, 1
        const bool hi = (lane >> k) & 1;
        #pragma unroll
        for (int q = 0; q < half; q++) {
            float send  = hi ? s[q] : s[q + half];
            float other = __shfl_xor_sync(0xffffffffu, send, 1 << k);
            s[q] = (hi ? s[q + half] : s[q]) + other;
        }
    }
    s[0] += __shfl_xor_sync(0xffffffffu, s[0], 8);
    s[0] += __shfl_xor_sync(0xffffffffu, s[0], 16);

    if (lane < 8) {
        // channel held by this lane: ch = bit0*4 + bit1*2 + bit2 (bit-reversed)
        int ch = ((lane & 1) << 2) | (lane & 2) | ((lane >> 2) & 1);
        // scale: 2^(1-zeta) (unordered-pair sum): ch%4 -> {1, 0.5, 0.125, 0.125}
        float scl = (ch & 2) ? 0.125f : ((ch & 1) ? 0.5f : 1.0f);
        atomicAdd(&out[i * 22 + 14 + ch], s[0] * scl);
    }
}

extern "C" void kernel_launch(void* const* d_in, const int* in_sizes, int n_in,
                              void* d_out, int out_size)
{
    const float* atomic_numbers = (const float*)d_in[0]; // [320,1]
    const float* coordinates    = (const float*)d_in[1]; // [320,3]
    float* out = (float*)d_out;                          // [320,22]
    featurizer_kernel<<<N_ATOMS, NTHREADS>>>(atomic_numbers, coordinates, out);
}